// round 7
// baseline (speedup 1.0000x reference)
#include <cuda_runtime.h>
#include <cstdint>

#define FM 0xffffffffu
#define NW 32
#define INFV 1000000000.0f
#define KMASK 0xFFFFFFE0u   // key: high 27 bits value, low 5 bits lane

struct Feat {
    float cx, cy, area, sr, ar, bx, by, prob;
};

__device__ __forceinline__ Feat wall_features(const float* __restrict__ q) {
    float sx = q[0], sy = q[1], ex = q[2], ey = q[3], w = q[4], prob = q[5];
    float dx = ex - sx, dy = ey - sy;
    float len = sqrtf(dx * dx + dy * dy);
    float cx = (sx + ex) * 0.5f, cy = (sy + ey) * 0.5f;
    float area = len * w;
    float smaller = fminf(w, len), bigger = fmaxf(w, len);
    float sr = (bigger > 0.0f) ? (smaller / bigger) : 0.0f;
    float px, py;
    if (len > 0.0f) {
        float s = w * 0.5f / len;
        px = dy * s;
        py = -dx * s;
    } else {
        px = 0.0f;
        py = 0.0f;
    }
    float right = fmaxf(fmaxf(sx + px, sx - px), fmaxf(ex + px, ex - px));
    float top   = fmaxf(fmaxf(sy + py, sy - py), fmaxf(ey + py, ey - py));
    float bbw = fabsf((right - cx) * 2.0f);
    float bbh = fabsf((top  - cy) * 2.0f);
    float bba = bbw * bbh;
    float ar = (bba > 0.001f) ? (area / bba) : 1.0f;
    Feat f;
    f.cx = cx; f.cy = cy; f.area = area; f.sr = sr; f.ar = ar;
    f.bx = bbw; f.by = bbh; f.prob = prob;
    return f;
}

// One warp per batch; columns (pred walls) <-> lanes.
// LAPJV: column reduction -> augmenting row reduction (min1/min2, tie-safe,
// breadth requeue) -> shortest augmenting paths with biased positive slacks.
__global__ void __launch_bounds__(32)
floorplanet_kernel(const float* __restrict__ params_true,
                   const float* __restrict__ params_pred,
                   float* __restrict__ out) {
    __shared__ float C[NW * NW];
    __shared__ int c4r_sh[NW];

    const int b = blockIdx.x;
    const int lane = threadIdx.x;

    Feat ft = wall_features(params_true + (size_t)b * NW * 6 + lane * 6);
    Feat fp = wall_features(params_pred + (size_t)b * NW * 6 + lane * 6);

    // Fill C[i][lane]; track column min on the fly.
    float cm = INFV;
    int am = 0;
#pragma unroll 4
    for (int i = 0; i < NW; i++) {
        float icx   = __shfl_sync(FM, ft.cx,   i);
        float icy   = __shfl_sync(FM, ft.cy,   i);
        float iarea = __shfl_sync(FM, ft.area, i);
        float isr   = __shfl_sync(FM, ft.sr,   i);
        float iar   = __shfl_sync(FM, ft.ar,   i);
        float ibx   = __shfl_sync(FM, ft.bx,   i);
        float iby   = __shfl_sync(FM, ft.by,   i);
        float iprob = __shfl_sync(FM, ft.prob, i);

        float dcx = icx - fp.cx, dcy = icy - fp.cy;
        float center_d = dcx * dcx + dcy * dcy;
        float da = iarea - fp.area;
        float ds = isr   - fp.sr;
        float dr = iar   - fp.ar;
        float dh = ibx   - fp.bx;
        float dv = iby   - fp.by;
        float dp = iprob - fp.prob;

        float param_d = da * da + center_d + dr * dr + dh * dh + dv * dv + ds * ds;
        float cost = 10.0f * (dp * dp) + param_d * iprob;
        C[i * NW + lane] = cost;
        if (cost < cm) { cm = cost; am = i; }
    }
    __syncwarp();

    // ---- Phase 1: column reduction. v[j]=colmin, greedily match argmin rows.
    float v = cm, u = 0.0f;
    unsigned grp = __match_any_sync(FM, am);
    bool winner = ((__ffs(grp) - 1) == lane);
    int row4col = winner ? am : -1;
    c4r_sh[lane] = -1;
    __syncwarp();
    if (winner) c4r_sh[am] = lane;
    __syncwarp();
    int col4row = c4r_sh[lane];

    // ---- Phase 2: augmenting row reduction (LAPJV). For each free row:
    // min1/min2 of reduced costs; u[i]=min2; take j1 (adjust v[j1]) and kick
    // its owner to the queue tail. Quantized ties on an owned column are NOT
    // kicked (ping-pong guard) -> deferred to SAP with feasible duals.
    // v only decreases, so d = C - v stays >= 0 (raw-bit uint ordering valid).
    unsigned freeq = __ballot_sync(FM, col4row < 0);
    unsigned sap = 0u;
    int guard = 64;
    while (freeq) {
        const int i = __ffs(freeq) - 1;
        freeq &= freeq - 1;
        if (--guard < 0) { sap |= (1u << i) | freeq; break; }

        float d = C[i * NW + lane] - v;
        unsigned key = (__float_as_uint(d) & KMASK) | (unsigned)lane;
        unsigned k1 = __reduce_min_sync(FM, key);
        int j1 = k1 & 31;
        unsigned keyx = (lane == j1) ? 0xFFFFFFFFu : key;
        unsigned k2 = __reduce_min_sync(FM, keyx);
        unsigned q1 = k1 & KMASK, q2 = k2 & KMASK;
        int r1 = __shfl_sync(FM, row4col, j1);

        if (lane == i) u = __uint_as_float(q2);   // u[i] = second min (feasible)
        if (r1 >= 0 && q1 == q2) {                // tie on owned column: defer
            sap |= 1u << i;
            continue;
        }
        if (lane == j1) {
            v -= __uint_as_float(q2) - __uint_as_float(q1);  // slack(i,j1) -> ~0
            row4col = i;
        }
        if (lane == i) col4row = j1;
        if (r1 >= 0) {                            // kick owner to queue tail
            if (lane == r1) col4row = -1;
            freeq |= 1u << r1;
        }
    }

    // ---- Phase 3: shortest augmenting path, biased slacks (slackb = slack+1).
    unsigned freerows = sap;
    while (freerows) {
        const int i0 = __ffs(freerows) - 1;
        freerows &= freerows - 1;

        float ur = __shfl_sync(FM, u, row4col & 31);  // u[row4col[lane]]
        float ui = __shfl_sync(FM, u, i0);
        unsigned SR = 0u, SC = 0u;
        unsigned mkey = 0xFFFFFFFFu;
        unsigned laneor = (unsigned)lane;   // ~0 once lane enters SC
        float spcb = INFV;
        int path = -1;
        float minValb = 1.0f;
        float sub = (ui - 1.0f) + v;        // slackb = C - sub, lane-local v
        int i = i0, sink = -1;

        do {
            SR |= 1u << i;
            float slackb = C[i * NW + lane] - sub;        // ~>= 1 > 0 always
            unsigned skey = (__float_as_uint(slackb) & KMASK) | laneor;
            if (skey < mkey) {              // off-chain: feeds post-loop only
                spcb = __uint_as_float(skey & KMASK);
                path = i;
            }
            mkey = umin(mkey, skey);
            unsigned om = __reduce_min_sync(FM, mkey);
            int j = om & 31;
            minValb = __uint_as_float(om & KMASK);
            SC |= 1u << j;
            if (lane == j) { laneor = 0xFFFFFFFFu; mkey = 0xFFFFFFFFu; }
            int r     = __shfl_sync(FM, row4col, j);      // overlapping shfls
            float urj = __shfl_sync(FM, ur, j);
            sub = (urj - minValb) + v;      // lane-local v; in LDS shadow
            if (r < 0) sink = j;
            i = r;
        } while (sink < 0);

        // Dual updates: bias cancels in differences; only u[i0] needs -1.
        float spcb_c4r = __shfl_sync(FM, spcb, col4row & 31);
        if ((SR >> lane) & 1u)
            u += (lane == i0) ? (minValb - 1.0f) : (minValb - spcb_c4r);
        if ((SC >> lane) & 1u) v -= minValb - spcb;

        // Augment along alternating path.
        int j = sink;
        bool done = false;
        while (!done) {
            int pi = __shfl_sync(FM, path, j);
            if (lane == j) row4col = pi;
            int jn = __shfl_sync(FM, col4row, pi);
            if (lane == pi) col4row = j;
            done = (pi == i0);
            j = jn;
        }
    }

    // loss = sum_i C[i][col4row[i]]
    float c = C[lane * NW + (col4row & 31)];
#pragma unroll
    for (int off = 16; off > 0; off >>= 1)
        c += __shfl_xor_sync(FM, c, off);
    if (lane == 0) out[b] = c;
}

extern "C" void kernel_launch(void* const* d_in, const int* in_sizes, int n_in,
                              void* d_out, int out_size) {
    const float* params_true = (const float*)d_in[0];
    const float* params_pred = (const float*)d_in[1];
    float* out = (float*)d_out;
    (void)in_sizes; (void)n_in; (void)out_size;
    floorplanet_kernel<<<2048, 32>>>(params_true, params_pred, out);
}